// round 8
// baseline (speedup 1.0000x reference)
#include <cuda_runtime.h>
#include <cstdint>

// MultiDirectionPattern: masked 8-direction pooling + saliency gather.
// 64-thread CTAs, 16 rows per warp (3136B bulk copy), two lanes per row
// (lane<16: dirs 0-3, lane>=16: dirs 4-7). smem 6.3KB/CTA and <=42 regs
// -> 24 CTAs/SM (48 warps). Feat path warp-autonomous: one cp.async.bulk
// per warp + per-warp mbarrier; mask verified against a constant bitmap
// while the copy flies. Sal gather reads s directly (each element read ~1x).

static constexpr int HW    = 49;     // 7*7
static constexpr int TPB   = 64;
static constexpr int SROW  = 3136;   // 56*56
static constexpr int WROWS = 16;     // rows per warp
static constexpr int WF    = WROWS * HW;   // 784 floats per warp slice
static constexpr int WBYTES = WF * 4;      // 3136 bytes
static constexpr int SM_FLOATS = 2 * WF;   // 1568 floats = 6272 B

// 392-bit bitmap of expected nonzero mask cells, word j serves verify
// iteration j: bit (p*49+k) of the stream set <=> feat_mask[p][k] != 0.
__constant__ uint32_t c_bits[13] = {
    0x0F000000u, 0x00010307u, 0xC3830200u, 0x04000003u, 0x0000F1C3u,
    0x20C38F00u, 0x1E1C1810u, 0xE1E00000u, 0x00002060u, 0x41871E00u,
    0x20000000u, 0x00078E18u, 0x00000000u
};

__device__ __forceinline__ void cp16(uint32_t dst, const void* src) {
    asm volatile("cp.async.cg.shared.global [%0], [%1], 16;\n" :: "r"(dst), "l"(src));
}
__device__ __forceinline__ void cp4(uint32_t dst, const void* src) {
    asm volatile("cp.async.ca.shared.global [%0], [%1], 4;\n" :: "r"(dst), "l"(src));
}
__device__ __forceinline__ void cp_commit() {
    asm volatile("cp.async.commit_group;\n" ::: "memory");
}
__device__ __forceinline__ void cp_wait_all() {
    asm volatile("cp.async.wait_group 0;\n" ::: "memory");
}
__device__ __forceinline__ void mbar_init(uint32_t mbar, uint32_t cnt) {
    asm volatile("mbarrier.init.shared.b64 [%0], %1;\n" :: "r"(mbar), "r"(cnt) : "memory");
}
__device__ __forceinline__ void fence_async() {
    asm volatile("fence.proxy.async.shared::cta;\n" ::: "memory");
}
__device__ __forceinline__ void mbar_expect_tx(uint32_t mbar, uint32_t bytes) {
    asm volatile("mbarrier.arrive.expect_tx.shared.b64 _, [%0], %1;\n"
                 :: "r"(mbar), "r"(bytes) : "memory");
}
__device__ __forceinline__ void cp_bulk(uint32_t dst, const void* src,
                                        uint32_t bytes, uint32_t mbar) {
    asm volatile("cp.async.bulk.shared::cta.global.mbarrier::complete_tx::bytes "
                 "[%0], [%1], %2, [%3];\n"
                 :: "r"(dst), "l"(src), "r"(bytes), "r"(mbar) : "memory");
}
__device__ __forceinline__ void mbar_wait(uint32_t mbar, uint32_t parity) {
    uint32_t done;
    asm volatile(
        "{\n\t.reg .pred p;\n\t"
        "mbarrier.try_wait.parity.acquire.cta.shared::cta.b64 p, [%1], %2;\n\t"
        "selp.b32 %0, 1, 0, p;\n\t}"
        : "=r"(done) : "r"(mbar), "r"(parity) : "memory");
    if (!done) {
        asm volatile(
            "{\n\t.reg .pred P1;\n\t"
            "WL_%=:\n\t"
            "mbarrier.try_wait.parity.acquire.cta.shared::cta.b64 P1, [%0], %1, 0x989680;\n\t"
            "@P1 bra.uni WD_%=;\n\t"
            "bra.uni WL_%=;\n\t"
            "WD_%=:\n\t}"
            :: "r"(mbar), "r"(parity) : "memory");
    }
}

__global__ __launch_bounds__(TPB, 24) void fused_kernel(
    const float* __restrict__ x,
    const float* __restrict__ s,
    const float* __restrict__ fm,
    const int*   __restrict__ sal_idx,
    float*       __restrict__ out,
    int rows,             // B*C
    int B,                // batch (sal blocks are blk < B)
    int N,                // saliency points per direction
    long long feat_elems  // rows*8
) {
    __shared__ __align__(16) float sm[SM_FLOATS];
    __shared__ __align__(8) unsigned long long smbar[2];
    const int blk = blockIdx.x;
    const int t   = threadIdx.x;

    if (blk >= B) {
        // ============ feat tile: warp-autonomous, 16 rows/warp ============
        const uint32_t sbase = (uint32_t)__cvta_generic_to_shared(sm);
        const uint32_t mbase = (uint32_t)__cvta_generic_to_shared(smbar);
        const int w    = t >> 5;
        const int lane = t & 31;
        const long long wrow0 = (long long)(blk - B) * (2 * WROWS) + (long long)w * WROWS;
        long long rem = rows - wrow0;
        if (rem <= 0) return;                    // no barriers in this path
        const int rh = rem < WROWS ? (int)rem : WROWS;

        float* wbuf = sm + w * WF;
        const uint32_t dst  = sbase + (uint32_t)w * WBYTES;
        const uint32_t mbar = mbase + (uint32_t)w * 8;
        const float* xw = x + wrow0 * HW;        // wrow0 mult of 16 -> 16B aligned
        const bool full = (rh == WROWS);

        if (full) {
            if (lane == 0) {
                mbar_init(mbar, 1);
                fence_async();
                mbar_expect_tx(mbar, WBYTES);
                cp_bulk(dst, xw, WBYTES, mbar);
            }
            __syncwarp();
        } else {
            const int total = rh * HW;
            const int n4 = total >> 2;
            const float4* xw4 = (const float4*)xw;
            for (int i = lane; i < n4; i += 32) cp16(dst + i * 16, xw4 + i);
            for (int i = 4 * n4 + lane; i < total; i += 32) cp4(dst + i * 4, xw + i);
            cp_commit();
        }

        // verify mask while the copy is in flight (bitmap words, no div/mod)
        int mybad = 0;
        #pragma unroll
        for (int j = 0; j < 13; ++j) {
            int i = lane + j * 32;
            if (i < 392) {
                float e = ((c_bits[j] >> lane) & 1u) ? 1.0f : 0.0f;
                if (__ldg(fm + i) != e) mybad = 1;
            }
        }
        const bool fb = __any_sync(0xffffffffu, mybad);

        if (full) mbar_wait(mbar, 0);
        else      { cp_wait_all(); __syncwarp(); }

        // two lanes per row: lane<16 -> dirs 0-3, lane>=16 -> dirs 4-7
        const int r = lane & 15;
        if (r < rh) {
            const float* xr = wbuf + r * HW;     // stride 49: conflict-free LDS
            float o0, o1, o2, o3;
            const float x24 = xr[24];
            if (!fb) {
                const float wgt = 0.1f;
                if (lane < 16) {
                    float R0 = xr[25] + xr[26] + xr[27];
                    float R1 = xr[32] + xr[40] + xr[48];
                    float R2 = xr[31] + xr[38] + xr[45];
                    float R3 = xr[30] + xr[36] + xr[42];
                    float R4 = xr[21] + xr[22] + xr[23];
                    float I0 = xr[33] + xr[34] + xr[41];
                    float I1 = xr[39] + xr[46] + xr[47];
                    float I2 = xr[37] + xr[43] + xr[44];
                    float I3 = xr[28] + xr[29] + xr[35];
                    o0 = (R0 + I0 + R1 + x24) * wgt;
                    o1 = (R1 + I1 + R2 + x24) * wgt;
                    o2 = (R2 + I2 + R3 + x24) * wgt;
                    o3 = (R3 + I3 + R4 + x24) * wgt;
                } else {
                    float R4 = xr[21] + xr[22] + xr[23];
                    float R5 = xr[ 0] + xr[ 8] + xr[16];
                    float R6 = xr[ 3] + xr[10] + xr[17];
                    float R7 = xr[ 6] + xr[12] + xr[18];
                    float R0 = xr[25] + xr[26] + xr[27];
                    float I4 = xr[ 7] + xr[14] + xr[15];
                    float I5 = xr[ 1] + xr[ 2] + xr[ 9];
                    float I6 = xr[ 4] + xr[ 5] + xr[11];
                    float I7 = xr[13] + xr[19] + xr[20];
                    o0 = (R4 + I4 + R5 + x24) * wgt;
                    o1 = (R5 + I5 + R6 + x24) * wgt;
                    o2 = (R6 + I6 + R7 + x24) * wgt;
                    o3 = (R7 + I7 + R0 + x24) * wgt;
                }
            } else {
                // generic dense fallback (rare): mask from gmem (cached)
                const int p0 = (lane < 16) ? 0 : 4;
                float a[4] = {0, 0, 0, 0};
                float c[4] = {0, 0, 0, 0};
                for (int k = 0; k < HW; ++k) {
                    float xv = xr[k];
                    #pragma unroll
                    for (int q = 0; q < 4; ++q) {
                        float m = __ldg(fm + (p0 + q) * HW + k);
                        a[q] += xv * m;
                        c[q] += (m != 0.0f) ? 1.0f : 0.0f;
                    }
                }
                o0 = a[0] / c[0]; o1 = a[1] / c[1];
                o2 = a[2] / c[2]; o3 = a[3] / c[3];
            }
            float* op = out + (wrow0 + r) * 8 + (lane >> 4) * 4;
            *(float4*)op = make_float4(o0, o1, o2, o3);
        }
    } else {
        // ============ sal gather: direct (no smem), one block per batch ====
        const int b = blk;
        const float* sb = s + (long long)b * SROW;
        float* ob = out + feat_elems + (long long)b * (8LL * N);
        for (int n = t; n < N; n += TPB) {
            float v[8];
            #pragma unroll
            for (int p = 0; p < 8; ++p)
                v[p] = __ldg(sb + __ldg(sal_idx + p * N + n));
            float4* op = (float4*)(ob + n * 8);
            op[0] = make_float4(v[0], v[1], v[2], v[3]);
            op[1] = make_float4(v[4], v[5], v[6], v[7]);
        }
    }
}

extern "C" void kernel_launch(void* const* d_in, const int* in_sizes, int n_in,
                              void* d_out, int out_size) {
    const float* x       = (const float*)d_in[0];
    const float* s       = (const float*)d_in[1];
    const float* fm      = (const float*)d_in[2];
    const int*   sal_idx = (const int*)d_in[3];
    float*       out     = (float*)d_out;

    const int rows = in_sizes[0] / HW;    // B*C
    const int B    = in_sizes[1] / SROW;  // batch
    const int N    = in_sizes[3] / 8;     // points per direction
    const int nfb  = (rows + 2 * WROWS - 1) / (2 * WROWS);
    const long long feat_elems = (long long)rows * 8;

    fused_kernel<<<B + nfb, TPB>>>(x, s, fm, sal_idx, out, rows, B, N, feat_elems);
}